// round 6
// baseline (speedup 1.0000x reference)
#include <cuda_runtime.h>
#include <stdint.h>

#define NCTA 128

// ----------------- device scratch (allocation-free) ------------------------
__device__ float g_emb [16384 * 512];     // embeddings / logits scratch
__device__ float g_seqA[16384 * 1024];    // layer sequence ping
__device__ float g_seqB[16384 * 1024];    // layer sequence pong
__device__ float g_xg  [16384 * 4096];    // gate preactivations [m][4H]
__device__ float g_hbuf[2][16 * 1024];    // double-buffered h
__device__ float g_hf0[16*1024], g_cf0[16*1024];
__device__ float g_hf1[16*1024], g_cf1[16*1024];
__device__ unsigned g_cnt;                // barrier ticket (self-resetting)
__device__ unsigned g_gen;                // barrier generation (monotonic)

// ----------------- embedding gather: g_emb[t*16+b][:] = emb[x[b][t]] -------
__global__ void __launch_bounds__(128) embed_k(const float* __restrict__ emb,
                                               const int* __restrict__ x) {
    int m = blockIdx.x;                 // m = t*16 + b
    int t = m >> 4, b = m & 15;
    int tok = x[b * 1024 + t];
    const float4* src = (const float4*)(emb + (size_t)tok * 512);
    float4* dst = (float4*)(g_emb + (size_t)m * 512);
    dst[threadIdx.x] = src[threadIdx.x];   // 128 threads * float4 = 512 floats
}

// ----------------- fp32 SGEMM (NT): C[m][n] = sum_k A[m][k]*B[n][k] + bias --
// M = 16384 fixed (grid.y = 128). K % 8 == 0, N % 128 == 0.
__global__ void __launch_bounds__(256) sgemm_nt(
    const float* __restrict__ A, const float* __restrict__ Bw,
    const float* __restrict__ b1, const float* __restrict__ b2,
    float* __restrict__ Cout, int K, int N)
{
    __shared__ float As[8][132];
    __shared__ float Bs[8][132];
    const int tid = threadIdx.x;
    const int row = tid >> 1;            // 0..127
    const int kc  = (tid & 1) * 4;       // 0 or 4
    const int m0 = blockIdx.y * 128;
    const int n0 = blockIdx.x * 128;
    const int ty = tid >> 4, tx = tid & 15;
    const float* Ag = A + (size_t)(m0 + row) * K + kc;
    const float* Bg = Bw + (size_t)(n0 + row) * K + kc;
    float acc[8][8];
    #pragma unroll
    for (int i = 0; i < 8; i++)
        #pragma unroll
        for (int j = 0; j < 8; j++) acc[i][j] = 0.f;

    for (int k0 = 0; k0 < K; k0 += 8) {
        float4 av = *(const float4*)(Ag + k0);
        float4 bv = *(const float4*)(Bg + k0);
        __syncthreads();
        As[kc+0][row] = av.x; As[kc+1][row] = av.y;
        As[kc+2][row] = av.z; As[kc+3][row] = av.w;
        Bs[kc+0][row] = bv.x; Bs[kc+1][row] = bv.y;
        Bs[kc+2][row] = bv.z; Bs[kc+3][row] = bv.w;
        __syncthreads();
        #pragma unroll
        for (int k = 0; k < 8; k++) {
            float4 a0 = *(const float4*)&As[k][ty*8];
            float4 a1 = *(const float4*)&As[k][ty*8+4];
            float4 c0 = *(const float4*)&Bs[k][tx*8];
            float4 c1 = *(const float4*)&Bs[k][tx*8+4];
            float ar[8] = {a0.x,a0.y,a0.z,a0.w,a1.x,a1.y,a1.z,a1.w};
            float br[8] = {c0.x,c0.y,c0.z,c0.w,c1.x,c1.y,c1.z,c1.w};
            #pragma unroll
            for (int i = 0; i < 8; i++)
                #pragma unroll
                for (int j = 0; j < 8; j++) acc[i][j] += ar[i]*br[j];
        }
    }
    float bb[8];
    #pragma unroll
    for (int j = 0; j < 8; j++) {
        int n = n0 + tx*8 + j;
        bb[j] = b1[n] + (b2 ? b2[n] : 0.f);
    }
    #pragma unroll
    for (int i = 0; i < 8; i++) {
        size_t base = (size_t)(m0 + ty*8 + i) * N + n0 + tx*8;
        float4 v0 = {acc[i][0]+bb[0], acc[i][1]+bb[1], acc[i][2]+bb[2], acc[i][3]+bb[3]};
        float4 v1 = {acc[i][4]+bb[4], acc[i][5]+bb[5], acc[i][6]+bb[6], acc[i][7]+bb[7]};
        *(float4*)&Cout[base]     = v0;
        *(float4*)&Cout[base + 4] = v1;
    }
}

// ----------------- software grid barrier (all 128 CTAs resident) ------------
__device__ __forceinline__ void gridbar(unsigned gen) {
    __threadfence();
    __syncthreads();
    if (threadIdx.x == 0) {
        unsigned t = atomicAdd(&g_cnt, 1);
        if (t == NCTA - 1) {
            g_cnt = 0;
            __threadfence();
            atomicExch(&g_gen, gen);
        } else {
            while ((int)(*(volatile unsigned*)&g_gen - gen) < 0)
                __nanosleep(64);
        }
        __threadfence();
    }
    __syncthreads();
}

// ----------------- persistent LSTM recurrence over T=1024 steps -------------
// CTA blk owns hidden units [blk*8, blk*8+8) across all 4 gates (32 Whh rows).
// Thread tid computes gate rows j0 = tid>>4 and j0+16 for batch b = tid&15.
// Threads < 128 own the (u = tid>>4, b = tid&15) cell state in a register.
__global__ void __launch_bounds__(256) recur_k(
    const float* __restrict__ xg,      // [16384][4096]
    const float* __restrict__ whh,     // [4096][1024]
    const float* __restrict__ hinit,   // [16][1024] or null (zeros)
    const float* __restrict__ cinit,   // [16][1024] or null (zeros)
    float* __restrict__ seq,           // [16384][1024]
    float* __restrict__ hfin, float* __restrict__ cfin)  // [16][1024] or null
{
    extern __shared__ float sm[];
    float* hs  = sm;            // [1024][16]  h transposed, conflict-free
    float* gsh = sm + 16384;    // [32][16]    gate exchange
    const int tid = threadIdx.x;
    const int blk = blockIdx.x;
    const int bb  = tid & 15;
    const int j0  = tid >> 4;          // 0..15
    const int j1  = j0 + 16;
    const int r0  = (j0 >> 3) * 1024 + blk * 8 + (j0 & 7);
    const int r1  = (j1 >> 3) * 1024 + blk * 8 + (j1 & 7);
    const float4* w0 = (const float4*)(whh + (size_t)r0 * 1024);
    const float4* w1 = (const float4*)(whh + (size_t)r1 * 1024);
    const int u  = tid >> 4;           // update threads: u 0..7
    const int hu = blk * 8 + u;

    float creg = 0.f, hlast = 0.f;
    unsigned gen = *(volatile unsigned*)&g_gen;   // stable: no CTA can advance yet

    if (tid < 128) {
        float h0 = 0.f;
        if (cinit) creg = cinit[bb * 1024 + hu];
        if (hinit) h0   = hinit[bb * 1024 + hu];
        g_hbuf[0][bb * 1024 + hu] = h0;
    }
    gen++; gridbar(gen);

    for (int t = 0; t < 1024; t++) {
        // load h (written by all CTAs last step) into shared, transposed
        {
            const float* hb = g_hbuf[t & 1];
            const int b = tid & 15, kb = tid >> 4;
            #pragma unroll
            for (int kk = 0; kk < 16; kk++) {
                int k4 = kb + kk * 16;
                float4 hv = __ldcg((const float4*)(hb + b * 1024 + k4 * 4));
                hs[(4*k4+0)*16+b] = hv.x; hs[(4*k4+1)*16+b] = hv.y;
                hs[(4*k4+2)*16+b] = hv.z; hs[(4*k4+3)*16+b] = hv.w;
            }
        }
        __syncthreads();

        const size_t m = (size_t)t * 16 + bb;
        float a0 = xg[m * 4096 + r0];
        float a1 = xg[m * 4096 + r1];
        #pragma unroll 4
        for (int k4 = 0; k4 < 256; k4++) {
            float4 wa = w0[k4];                 // L1-resident, 16-lane broadcast
            float4 wb = w1[k4];
            float h0v = hs[(4*k4+0)*16+bb];
            float h1v = hs[(4*k4+1)*16+bb];
            float h2v = hs[(4*k4+2)*16+bb];
            float h3v = hs[(4*k4+3)*16+bb];
            a0 += wa.x*h0v; a0 += wa.y*h1v; a0 += wa.z*h2v; a0 += wa.w*h3v;
            a1 += wb.x*h0v; a1 += wb.y*h1v; a1 += wb.z*h2v; a1 += wb.w*h3v;
        }
        gsh[j0*16 + bb] = a0;
        gsh[j1*16 + bb] = a1;
        __syncthreads();

        if (tid < 128) {
            float gi = gsh[(u     )*16 + bb];   // gate order: i, f, g, o
            float gf = gsh[(8  + u)*16 + bb];
            float gg = gsh[(16 + u)*16 + bb];
            float go = gsh[(24 + u)*16 + bb];
            float si = 1.f/(1.f + __expf(-gi));
            float sf = 1.f/(1.f + __expf(-gf));
            float so = 1.f/(1.f + __expf(-go));
            creg = sf*creg + si*tanhf(gg);
            float hv = so * tanhf(creg);
            hlast = hv;
            g_hbuf[(t+1) & 1][bb*1024 + hu] = hv;
            seq[m*1024 + hu] = hv;
        }
        gen++; gridbar(gen);
    }
    if (tid < 128) {
        if (hfin) hfin[bb*1024 + hu] = hlast;
        if (cfin) cfin[bb*1024 + hu] = creg;
    }
}

// ----------------- (B,T,C) -> (B,C,T) transpose ----------------------------
__global__ void __launch_bounds__(256) trans_k(const float* __restrict__ scr,
                                               float* __restrict__ out) {
    __shared__ float tile[32][33];
    int b  = blockIdx.z;
    int t0 = blockIdx.x * 32, n0 = blockIdx.y * 32;
    int tx = threadIdx.x, ty = threadIdx.y;
    for (int i = ty; i < 32; i += 8)
        tile[i][tx] = scr[((size_t)(t0 + i) * 16 + b) * 256 + n0 + tx];
    __syncthreads();
    for (int i = ty; i < 32; i += 8)
        out[((size_t)b * 256 + n0 + i) * 1024 + t0 + tx] = tile[tx][i];
}

// ----------------- driver ---------------------------------------------------
extern "C" void kernel_launch(void* const* d_in, const int* in_sizes, int n_in,
                              void* d_out, int out_size) {
    (void)in_sizes; (void)n_in; (void)out_size;
    const int*   x       = (const int*)  d_in[0];
    const float* enc_emb = (const float*)d_in[1];
    const float* dec_emb = (const float*)d_in[2];
    const float* eW0 = (const float*)d_in[3],  *eU0 = (const float*)d_in[4];
    const float* eb0 = (const float*)d_in[5],  *ec0 = (const float*)d_in[6];
    const float* eW1 = (const float*)d_in[7],  *eU1 = (const float*)d_in[8];
    const float* eb1 = (const float*)d_in[9],  *ec1 = (const float*)d_in[10];
    const float* dW0 = (const float*)d_in[11], *dU0 = (const float*)d_in[12];
    const float* db0 = (const float*)d_in[13], *dc0 = (const float*)d_in[14];
    const float* dW1 = (const float*)d_in[15], *dU1 = (const float*)d_in[16];
    const float* db1 = (const float*)d_in[17], *dc1 = (const float*)d_in[18];
    const float* outW = (const float*)d_in[19];
    const float* outb = (const float*)d_in[20];
    float* out = (float*)d_out;

    static int smem_set = 0;
    if (!smem_set) {
        cudaFuncSetAttribute(recur_k, cudaFuncAttributeMaxDynamicSharedMemorySize, 67584);
        smem_set = 1;
    }

    float *emb, *seqA, *seqB, *xgp, *hf0, *cf0, *hf1, *cf1;
    cudaGetSymbolAddress((void**)&emb,  g_emb);
    cudaGetSymbolAddress((void**)&seqA, g_seqA);
    cudaGetSymbolAddress((void**)&seqB, g_seqB);
    cudaGetSymbolAddress((void**)&xgp,  g_xg);
    cudaGetSymbolAddress((void**)&hf0,  g_hf0);
    cudaGetSymbolAddress((void**)&cf0,  g_cf0);
    cudaGetSymbolAddress((void**)&hf1,  g_hf1);
    cudaGetSymbolAddress((void**)&cf1,  g_cf1);

    const dim3 gBig(32, 128), gOut(2, 128);

    // Encoder
    embed_k<<<16384, 128>>>(enc_emb, x);
    sgemm_nt<<<gBig, 256>>>(emb,  eW0, eb0, ec0, xgp, 512,  4096);
    recur_k<<<NCTA, 256, 67584>>>(xgp, eU0, nullptr, nullptr, seqA, hf0, cf0);
    sgemm_nt<<<gBig, 256>>>(seqA, eW1, eb1, ec1, xgp, 1024, 4096);
    recur_k<<<NCTA, 256, 67584>>>(xgp, eU1, nullptr, nullptr, seqB, hf1, cf1);
    // Decoder (teacher forcing, states from encoder)
    embed_k<<<16384, 128>>>(dec_emb, x);
    sgemm_nt<<<gBig, 256>>>(emb,  dW0, db0, dc0, xgp, 512,  4096);
    recur_k<<<NCTA, 256, 67584>>>(xgp, dU0, hf0, cf0, seqA, nullptr, nullptr);
    sgemm_nt<<<gBig, 256>>>(seqA, dW1, db1, dc1, xgp, 1024, 4096);
    recur_k<<<NCTA, 256, 67584>>>(xgp, dU1, hf1, cf1, seqB, nullptr, nullptr);
    // Output projection into scratch (g_emb), then transpose to (B,C,T)
    sgemm_nt<<<gOut, 256>>>(seqB, outW, outb, nullptr, emb, 1024, 256);
    trans_k<<<dim3(32, 8, 16), dim3(32, 8)>>>(emb, out);
}

// round 10
// speedup vs baseline: 2.6037x; 2.6037x over previous
#include <cuda_runtime.h>
#include <stdint.h>

#define NCTA 128
#define STR_W 1036   // padded row stride (floats) for weight smem: 8 distinct banks across r
#define STR_H 1036   // padded row stride for h smem: bq banks 0,12,24,4

// FMA2 helpers (packed fp32x2, sm_100+)
#define FMA2(acc, a, b) asm("fma.rn.f32x2 %0, %1, %2, %0;" : "+l"(acc) : "l"(a), "l"(b))
#define DUP2(d, s)      asm("mov.b64 %0, {%1, %1};"        : "=l"(d)   : "f"(s))
#define UNPK(lo, hi, v) asm("mov.b64 {%0, %1}, %2;" : "=f"(lo), "=f"(hi) : "l"(v))

// ----------------- device scratch (allocation-free) ------------------------
__device__ float g_emb [16384 * 512];     // embeddings / logits scratch
__device__ float g_seqA[16384 * 1024];    // layer sequence ping
__device__ float g_seqB[16384 * 1024];    // layer sequence pong
__device__ float g_xg  [16384 * 4096];    // gate preactivations [m][4H]
__device__ float g_hbuf[2][16 * 1024];    // double-buffered h, batch-major [b][k]
__device__ float g_hf0[16*1024], g_cf0[16*1024];
__device__ float g_hf1[16*1024], g_cf1[16*1024];
__device__ unsigned g_cnt;                // barrier ticket (self-resetting)
__device__ unsigned g_gen;                // barrier generation (monotonic)

// ----------------- embedding gather: g_emb[t*16+b][:] = emb[x[b][t]] -------
__global__ void __launch_bounds__(128) embed_k(const float* __restrict__ emb,
                                               const int* __restrict__ x) {
    int m = blockIdx.x;                 // m = t*16 + b
    int t = m >> 4, b = m & 15;
    int tok = x[b * 1024 + t];
    const float4* src = (const float4*)(emb + (size_t)tok * 512);
    float4* dst = (float4*)(g_emb + (size_t)m * 512);
    dst[threadIdx.x] = src[threadIdx.x];   // 128 threads * float4 = 512 floats
}

// ----------------- fp32 SGEMM (NT) with f32x2 FMA: C = A*B^T + bias --------
// M = 16384 fixed (grid.y = 128). K % 8 == 0, N % 128 == 0.
__global__ void __launch_bounds__(256, 2) sgemm_nt(
    const float* __restrict__ A, const float* __restrict__ Bw,
    const float* __restrict__ b1, const float* __restrict__ b2,
    float* __restrict__ Cout, int K, int N)
{
    __shared__ float As[2][8][132];
    __shared__ float Bs[2][8][132];
    const int tid = threadIdx.x;
    const int row = tid >> 1;            // 0..127
    const int kc  = (tid & 1) * 4;       // 0 or 4
    const int m0 = blockIdx.y * 128;
    const int n0 = blockIdx.x * 128;
    const int ty = tid >> 4, tx = tid & 15;
    const float* Ag = A  + (size_t)(m0 + row) * K + kc;
    const float* Bg = Bw + (size_t)(n0 + row) * K + kc;

    unsigned long long acc2[4][8];       // [m-pair][n], lo = even m, hi = odd m
    #pragma unroll
    for (int i = 0; i < 4; i++)
        #pragma unroll
        for (int j = 0; j < 8; j++) acc2[i][j] = 0ull;

    // prologue: fill buffer 0
    {
        float4 av = *(const float4*)Ag;
        float4 bv = *(const float4*)Bg;
        As[0][kc+0][row] = av.x; As[0][kc+1][row] = av.y;
        As[0][kc+2][row] = av.z; As[0][kc+3][row] = av.w;
        Bs[0][kc+0][row] = bv.x; Bs[0][kc+1][row] = bv.y;
        Bs[0][kc+2][row] = bv.z; Bs[0][kc+3][row] = bv.w;
    }
    const int nb = K >> 3;
    for (int i = 0; i < nb; i++) {
        __syncthreads();
        float4 av2, bv2;
        if (i + 1 < nb) {
            av2 = *(const float4*)(Ag + (i + 1) * 8);
            bv2 = *(const float4*)(Bg + (i + 1) * 8);
        }
        const int p = i & 1;
        #pragma unroll
        for (int k = 0; k < 8; k++) {
            const float* as = &As[p][k][ty * 8];
            ulonglong2 a01 = *(const ulonglong2*)as;
            ulonglong2 a23 = *(const ulonglong2*)(as + 4);
            const float* bs = &Bs[p][k][tx * 8];
            float4 c0 = *(const float4*)bs;
            float4 c1 = *(const float4*)(bs + 4);
            float brr[8] = {c0.x,c0.y,c0.z,c0.w,c1.x,c1.y,c1.z,c1.w};
            unsigned long long bd[8];
            #pragma unroll
            for (int j = 0; j < 8; j++) {
                DUP2(bd[j], brr[j]);
                FMA2(acc2[0][j], a01.x, bd[j]);
                FMA2(acc2[1][j], a01.y, bd[j]);
                FMA2(acc2[2][j], a23.x, bd[j]);
                FMA2(acc2[3][j], a23.y, bd[j]);
            }
        }
        if (i + 1 < nb) {
            const int np = (i + 1) & 1;
            As[np][kc+0][row] = av2.x; As[np][kc+1][row] = av2.y;
            As[np][kc+2][row] = av2.z; As[np][kc+3][row] = av2.w;
            Bs[np][kc+0][row] = bv2.x; Bs[np][kc+1][row] = bv2.y;
            Bs[np][kc+2][row] = bv2.z; Bs[np][kc+3][row] = bv2.w;
        }
    }

    float accf[8][8];
    #pragma unroll
    for (int ip = 0; ip < 4; ip++)
        #pragma unroll
        for (int j = 0; j < 8; j++)
            UNPK(accf[2*ip][j], accf[2*ip+1][j], acc2[ip][j]);

    float bb[8];
    #pragma unroll
    for (int j = 0; j < 8; j++) {
        int n = n0 + tx*8 + j;
        bb[j] = b1[n] + (b2 ? b2[n] : 0.f);
    }
    #pragma unroll
    for (int i = 0; i < 8; i++) {
        size_t base = (size_t)(m0 + ty*8 + i) * N + n0 + tx*8;
        float4 v0 = {accf[i][0]+bb[0], accf[i][1]+bb[1], accf[i][2]+bb[2], accf[i][3]+bb[3]};
        float4 v1 = {accf[i][4]+bb[4], accf[i][5]+bb[5], accf[i][6]+bb[6], accf[i][7]+bb[7]};
        *(float4*)&Cout[base]     = v0;
        *(float4*)&Cout[base + 4] = v1;
    }
}

// ----------------- software grid barrier (all 128 CTAs resident) ------------
__device__ __forceinline__ void gridbar(unsigned gen) {
    __threadfence();
    __syncthreads();
    if (threadIdx.x == 0) {
        unsigned t = atomicAdd(&g_cnt, 1);
        if (t == NCTA - 1) {
            g_cnt = 0;
            __threadfence();
            atomicExch(&g_gen, gen);
        } else {
            while ((int)(*(volatile unsigned*)&g_gen - gen) < 0)
                __nanosleep(64);
        }
        __threadfence();
    }
    __syncthreads();
}

// ----------------- persistent LSTM recurrence over T=1024 steps -------------
// CTA blk owns hidden units [blk*8, blk*8+8) across 4 gates (32 Whh rows).
// Whh slice lives in SMEM (loaded once). 512 threads:
//   q = tid>>7 (K quarter), idx = tid&127, r = idx>>2 (gate row), bq = idx&3.
//   Thread computes row r for batches {bq, bq+4, bq+8, bq+12} over 256 ks,
//   with k-pairs packed into fma.rn.f32x2. K-quarters reduced via smem.
__global__ void __launch_bounds__(512, 1) recur_k(
    const float* __restrict__ xg,      // [16384][4096]
    const float* __restrict__ whh,     // [4096][1024]
    const float* __restrict__ hinit,   // [16][1024] or null (zeros)
    const float* __restrict__ cinit,   // [16][1024] or null (zeros)
    float* __restrict__ seq,           // [16384][1024]
    float* __restrict__ hfin, float* __restrict__ cfin)  // [16][1024] or null
{
    extern __shared__ float sm[];
    float* w_s = sm;                         // 32 * 1036
    float* hs  = sm + 32 * STR_W;            // 16 * 1036
    float* gsh = hs + 16 * STR_H;            // 512  (32 rows x 16 batch)
    float* red = gsh + 512;                  // 2048 (512 threads x 4)

    const int tid = threadIdx.x;
    const int blk = blockIdx.x;

    // prologue: stage Whh slice into smem (coalesced per row)
    {
        int wr = tid >> 4, wc = tid & 15;
        int grow = (wr >> 3) * 1024 + blk * 8 + (wr & 7);
        const float4* src = (const float4*)(whh + (size_t)grow * 1024);
        #pragma unroll
        for (int j = 0; j < 16; j++) {
            float4 v = src[wc + j * 16];
            *(float4*)&w_s[wr * STR_W + (wc + j * 16) * 4] = v;
        }
    }

    const int q = tid >> 7, idx = tid & 127;
    const int r = idx >> 2, bq = idx & 3;
    const int kbase = q * 256;
    const float* wrow = w_s + r * STR_W;
    const int grow_r = (r >> 3) * 1024 + blk * 8 + (r & 7);  // xg row for reducer

    const int u = tid >> 4, ub = tid & 15;   // updater mapping (tid<128: u 0..7)
    const int hu = blk * 8 + u;

    float creg = 0.f, hlast = 0.f;
    unsigned gen = *(volatile unsigned*)&g_gen;  // stable: no CTA can advance yet

    if (tid < 128) {
        float h0 = 0.f;
        if (cinit) creg = cinit[ub * 1024 + hu];
        if (hinit) h0   = hinit[ub * 1024 + hu];
        g_hbuf[0][ub * 1024 + hu] = h0;
    }
    gen++; gridbar(gen);

    for (int t = 0; t < 1024; t++) {
        // prefetch xg for this step's reducers (hidden under the FMA loop)
        float xr0, xr1, xr2, xr3;
        if (tid < 128) {
            const float* xp = xg + ((size_t)(t * 16 + bq)) * 4096 + grow_r;
            xr0 = __ldcg(xp);
            xr1 = __ldcg(xp + 4  * 4096);
            xr2 = __ldcg(xp + 8  * 4096);
            xr3 = __ldcg(xp + 12 * 4096);
        }
        // coalesced copy of h (batch-major) into padded smem
        {
            const float4* hb = (const float4*)g_hbuf[t & 1];
            #pragma unroll
            for (int i = 0; i < 8; i++) {
                int v = tid + i * 512;          // 4096 float4s
                float4 hv = __ldcg(hb + v);
                int b = v >> 8, k4 = v & 255;
                *(float4*)&hs[b * STR_H + k4 * 4] = hv;
            }
        }
        __syncthreads();

        // packed-k FMA2 mainloop: 8 FMA2 (=16 FMA) per k4 per thread
        unsigned long long a0 = 0ull, a1 = 0ull, a2 = 0ull, a3 = 0ull;
        const float* h0p = hs + (bq     ) * STR_H;
        const float* h1p = hs + (bq +  4) * STR_H;
        const float* h2p = hs + (bq +  8) * STR_H;
        const float* h3p = hs + (bq + 12) * STR_H;
        #pragma unroll 4
        for (int k = kbase; k < kbase + 256; k += 4) {
            ulonglong2 wv = *(const ulonglong2*)&wrow[k];
            ulonglong2 h0 = *(const ulonglong2*)&h0p[k];
            ulonglong2 h1 = *(const ulonglong2*)&h1p[k];
            ulonglong2 h2 = *(const ulonglong2*)&h2p[k];
            ulonglong2 h3 = *(const ulonglong2*)&h3p[k];
            FMA2(a0, wv.x, h0.x); FMA2(a0, wv.y, h0.y);
            FMA2(a1, wv.x, h1.x); FMA2(a1, wv.y, h1.y);
            FMA2(a2, wv.x, h2.x); FMA2(a2, wv.y, h2.y);
            FMA2(a3, wv.x, h3.x); FMA2(a3, wv.y, h3.y);
        }
        float p0, p1, p2, p3;
        { float lo, hi;
          UNPK(lo, hi, a0); p0 = lo + hi;
          UNPK(lo, hi, a1); p1 = lo + hi;
          UNPK(lo, hi, a2); p2 = lo + hi;
          UNPK(lo, hi, a3); p3 = lo + hi; }
        float4 pv = {p0, p1, p2, p3};
        *(float4*)&red[tid * 4] = pv;
        __syncthreads();

        if (tid < 128) {     // reduce K quarters + add xg -> gate preacts
            float4 s0 = *(const float4*)&red[tid * 4];
            float4 s1 = *(const float4*)&red[512  + tid * 4];
            float4 s2 = *(const float4*)&red[1024 + tid * 4];
            float4 s3 = *(const float4*)&red[1536 + tid * 4];
            gsh[r * 16 + bq     ] = s0.x + s1.x + s2.x + s3.x + xr0;
            gsh[r * 16 + bq +  4] = s0.y + s1.y + s2.y + s3.y + xr1;
            gsh[r * 16 + bq +  8] = s0.z + s1.z + s2.z + s3.z + xr2;
            gsh[r * 16 + bq + 12] = s0.w + s1.w + s2.w + s3.w + xr3;
        }
        __syncthreads();

        if (tid < 128) {     // cell update (gate order: i, f, g, o)
            float gi = gsh[(u     ) * 16 + ub];
            float gf = gsh[(8  + u) * 16 + ub];
            float gg = gsh[(16 + u) * 16 + ub];
            float go = gsh[(24 + u) * 16 + ub];
            float si = 1.f / (1.f + __expf(-gi));
            float sf = 1.f / (1.f + __expf(-gf));
            float so = 1.f / (1.f + __expf(-go));
            creg = sf * creg + si * tanhf(gg);
            float hv = so * tanhf(creg);
            hlast = hv;
            g_hbuf[(t + 1) & 1][ub * 1024 + hu] = hv;
            seq[((size_t)(t * 16 + ub)) * 1024 + hu] = hv;
        }
        gen++; gridbar(gen);
    }
    if (tid < 128) {
        if (hfin) hfin[ub * 1024 + hu] = hlast;
        if (cfin) cfin[ub * 1024 + hu] = creg;
    }
}

// ----------------- (B,T,C) -> (B,C,T) transpose ----------------------------
__global__ void __launch_bounds__(256) trans_k(const float* __restrict__ scr,
                                               float* __restrict__ out) {
    __shared__ float tile[32][33];
    int b  = blockIdx.z;
    int t0 = blockIdx.x * 32, n0 = blockIdx.y * 32;
    int tx = threadIdx.x, ty = threadIdx.y;
    for (int i = ty; i < 32; i += 8)
        tile[i][tx] = scr[((size_t)(t0 + i) * 16 + b) * 256 + n0 + tx];
    __syncthreads();
    for (int i = ty; i < 32; i += 8)
        out[((size_t)b * 256 + n0 + i) * 1024 + t0 + tx] = tile[tx][i];
}

// ----------------- driver ---------------------------------------------------
extern "C" void kernel_launch(void* const* d_in, const int* in_sizes, int n_in,
                              void* d_out, int out_size) {
    (void)in_sizes; (void)n_in; (void)out_size;
    const int*   x       = (const int*)  d_in[0];
    const float* enc_emb = (const float*)d_in[1];
    const float* dec_emb = (const float*)d_in[2];
    const float* eW0 = (const float*)d_in[3],  *eU0 = (const float*)d_in[4];
    const float* eb0 = (const float*)d_in[5],  *ec0 = (const float*)d_in[6];
    const float* eW1 = (const float*)d_in[7],  *eU1 = (const float*)d_in[8];
    const float* eb1 = (const float*)d_in[9],  *ec1 = (const float*)d_in[10];
    const float* dW0 = (const float*)d_in[11], *dU0 = (const float*)d_in[12];
    const float* db0 = (const float*)d_in[13], *dc0 = (const float*)d_in[14];
    const float* dW1 = (const float*)d_in[15], *dU1 = (const float*)d_in[16];
    const float* db1 = (const float*)d_in[17], *dc1 = (const float*)d_in[18];
    const float* outW = (const float*)d_in[19];
    const float* outb = (const float*)d_in[20];
    float* out = (float*)d_out;

    const int RSMEM = (32 * STR_W + 16 * STR_H + 512 + 2048) * 4;  // 209,152 B

    static int smem_set = 0;
    if (!smem_set) {
        cudaFuncSetAttribute(recur_k, cudaFuncAttributeMaxDynamicSharedMemorySize, RSMEM);
        smem_set = 1;
    }

    float *emb, *seqA, *seqB, *xgp, *hf0, *cf0, *hf1, *cf1;
    cudaGetSymbolAddress((void**)&emb,  g_emb);
    cudaGetSymbolAddress((void**)&seqA, g_seqA);
    cudaGetSymbolAddress((void**)&seqB, g_seqB);
    cudaGetSymbolAddress((void**)&xgp,  g_xg);
    cudaGetSymbolAddress((void**)&hf0,  g_hf0);
    cudaGetSymbolAddress((void**)&cf0,  g_cf0);
    cudaGetSymbolAddress((void**)&hf1,  g_hf1);
    cudaGetSymbolAddress((void**)&cf1,  g_cf1);

    const dim3 gBig(32, 128), gOut(2, 128);

    // Encoder
    embed_k<<<16384, 128>>>(enc_emb, x);
    sgemm_nt<<<gBig, 256>>>(emb,  eW0, eb0, ec0, xgp, 512,  4096);
    recur_k<<<NCTA, 512, RSMEM>>>(xgp, eU0, nullptr, nullptr, seqA, hf0, cf0);
    sgemm_nt<<<gBig, 256>>>(seqA, eW1, eb1, ec1, xgp, 1024, 4096);
    recur_k<<<NCTA, 512, RSMEM>>>(xgp, eU1, nullptr, nullptr, seqB, hf1, cf1);
    // Decoder (teacher forcing, states from encoder)
    embed_k<<<16384, 128>>>(dec_emb, x);
    sgemm_nt<<<gBig, 256>>>(emb,  dW0, db0, dc0, xgp, 512,  4096);
    recur_k<<<NCTA, 512, RSMEM>>>(xgp, dU0, hf0, cf0, seqA, nullptr, nullptr);
    sgemm_nt<<<gBig, 256>>>(seqA, dW1, db1, dc1, xgp, 1024, 4096);
    recur_k<<<NCTA, 512, RSMEM>>>(xgp, dU1, hf1, cf1, seqB, nullptr, nullptr);
    // Output projection into scratch (g_emb), then transpose to (B,C,T)
    sgemm_nt<<<gOut, 256>>>(seqB, outW, outb, nullptr, emb, 1024, 256);
    trans_k<<<dim3(32, 8, 16), dim3(32, 8)>>>(emb, out);
}

// round 12
// speedup vs baseline: 2.6075x; 1.0015x over previous
#include <cuda_runtime.h>
#include <stdint.h>

#define NCTA 128
#define STR_W 1036   // padded row stride (floats) for weight smem: 8 distinct banks across r
#define STR_H 1036   // padded row stride for h smem: bq banks 0,12,24,4

// FMA2 helpers (packed fp32x2, sm_100+)
#define FMA2(acc, a, b) asm("fma.rn.f32x2 %0, %1, %2, %0;" : "+l"(acc) : "l"(a), "l"(b))
#define DUP2(d, s)      asm("mov.b64 %0, {%1, %1};"        : "=l"(d)   : "f"(s))
#define UNPK(lo, hi, v) asm("mov.b64 {%0, %1}, %2;" : "=f"(lo), "=f"(hi) : "l"(v))

// ----------------- device scratch (allocation-free) ------------------------
__device__ float g_emb [16384 * 512];     // embeddings / logits scratch
__device__ float g_seqA[16384 * 1024];    // layer sequence ping
__device__ float g_seqB[16384 * 1024];    // layer sequence pong
__device__ float g_xg  [16384 * 4096];    // gate preactivations [m][4H]
__device__ float g_hbuf[2][16 * 1024];    // double-buffered h, batch-major [b][k]
__device__ float g_hf0[16*1024], g_cf0[16*1024];
__device__ float g_hf1[16*1024], g_cf1[16*1024];
__device__ unsigned g_cnt;                // barrier ticket (self-resetting)
__device__ unsigned g_gen;                // barrier generation (monotonic)

// ----------------- embedding gather: g_emb[t*16+b][:] = emb[x[b][t]] -------
__global__ void __launch_bounds__(128) embed_k(const float* __restrict__ emb,
                                               const int* __restrict__ x) {
    int m = blockIdx.x;                 // m = t*16 + b
    int t = m >> 4, b = m & 15;
    int tok = x[b * 1024 + t];
    const float4* src = (const float4*)(emb + (size_t)tok * 512);
    float4* dst = (float4*)(g_emb + (size_t)m * 512);
    dst[threadIdx.x] = src[threadIdx.x];   // 128 threads * float4 = 512 floats
}

// ----------------- fp32 SGEMM (NT) with f32x2 FMA: C = A*B^T + bias --------
// M = 16384 fixed (grid.y = 128). K % 8 == 0, N % 128 == 0.
__global__ void __launch_bounds__(256, 2) sgemm_nt(
    const float* __restrict__ A, const float* __restrict__ Bw,
    const float* __restrict__ b1, const float* __restrict__ b2,
    float* __restrict__ Cout, int K, int N)
{
    __shared__ float As[2][8][132];
    __shared__ float Bs[2][8][132];
    const int tid = threadIdx.x;
    const int row = tid >> 1;            // 0..127
    const int kc  = (tid & 1) * 4;       // 0 or 4
    const int m0 = blockIdx.y * 128;
    const int n0 = blockIdx.x * 128;
    const int ty = tid >> 4, tx = tid & 15;
    const float* Ag = A  + (size_t)(m0 + row) * K + kc;
    const float* Bg = Bw + (size_t)(n0 + row) * K + kc;

    unsigned long long acc2[4][8];       // [m-pair][n], lo = even m, hi = odd m
    #pragma unroll
    for (int i = 0; i < 4; i++)
        #pragma unroll
        for (int j = 0; j < 8; j++) acc2[i][j] = 0ull;

    // prologue: fill buffer 0
    {
        float4 av = *(const float4*)Ag;
        float4 bv = *(const float4*)Bg;
        As[0][kc+0][row] = av.x; As[0][kc+1][row] = av.y;
        As[0][kc+2][row] = av.z; As[0][kc+3][row] = av.w;
        Bs[0][kc+0][row] = bv.x; Bs[0][kc+1][row] = bv.y;
        Bs[0][kc+2][row] = bv.z; Bs[0][kc+3][row] = bv.w;
    }
    const int nb = K >> 3;
    for (int i = 0; i < nb; i++) {
        __syncthreads();
        float4 av2, bv2;
        if (i + 1 < nb) {
            av2 = *(const float4*)(Ag + (i + 1) * 8);
            bv2 = *(const float4*)(Bg + (i + 1) * 8);
        }
        const int p = i & 1;
        #pragma unroll
        for (int k = 0; k < 8; k++) {
            const float* as = &As[p][k][ty * 8];
            ulonglong2 a01 = *(const ulonglong2*)as;
            ulonglong2 a23 = *(const ulonglong2*)(as + 4);
            const float* bs = &Bs[p][k][tx * 8];
            float4 c0 = *(const float4*)bs;
            float4 c1 = *(const float4*)(bs + 4);
            float brr[8] = {c0.x,c0.y,c0.z,c0.w,c1.x,c1.y,c1.z,c1.w};
            unsigned long long bd[8];
            #pragma unroll
            for (int j = 0; j < 8; j++) {
                DUP2(bd[j], brr[j]);
                FMA2(acc2[0][j], a01.x, bd[j]);
                FMA2(acc2[1][j], a01.y, bd[j]);
                FMA2(acc2[2][j], a23.x, bd[j]);
                FMA2(acc2[3][j], a23.y, bd[j]);
            }
        }
        if (i + 1 < nb) {
            const int np = (i + 1) & 1;
            As[np][kc+0][row] = av2.x; As[np][kc+1][row] = av2.y;
            As[np][kc+2][row] = av2.z; As[np][kc+3][row] = av2.w;
            Bs[np][kc+0][row] = bv2.x; Bs[np][kc+1][row] = bv2.y;
            Bs[np][kc+2][row] = bv2.z; Bs[np][kc+3][row] = bv2.w;
        }
    }

    float accf[8][8];
    #pragma unroll
    for (int ip = 0; ip < 4; ip++)
        #pragma unroll
        for (int j = 0; j < 8; j++)
            UNPK(accf[2*ip][j], accf[2*ip+1][j], acc2[ip][j]);

    float bb[8];
    #pragma unroll
    for (int j = 0; j < 8; j++) {
        int n = n0 + tx*8 + j;
        bb[j] = b1[n] + (b2 ? b2[n] : 0.f);
    }
    #pragma unroll
    for (int i = 0; i < 8; i++) {
        size_t base = (size_t)(m0 + ty*8 + i) * N + n0 + tx*8;
        float4 v0 = {accf[i][0]+bb[0], accf[i][1]+bb[1], accf[i][2]+bb[2], accf[i][3]+bb[3]};
        float4 v1 = {accf[i][4]+bb[4], accf[i][5]+bb[5], accf[i][6]+bb[6], accf[i][7]+bb[7]};
        *(float4*)&Cout[base]     = v0;
        *(float4*)&Cout[base + 4] = v1;
    }
}

// ----------------- software grid barrier (all 128 CTAs resident) ------------
__device__ __forceinline__ void gridbar(unsigned gen) {
    __threadfence();
    __syncthreads();
    if (threadIdx.x == 0) {
        unsigned t = atomicAdd(&g_cnt, 1);
        if (t == NCTA - 1) {
            g_cnt = 0;
            __threadfence();
            atomicExch(&g_gen, gen);
        } else {
            while ((int)(*(volatile unsigned*)&g_gen - gen) < 0)
                __nanosleep(64);
        }
        __threadfence();
    }
    __syncthreads();
}

// ----------------- persistent LSTM recurrence over T=1024 steps -------------
// CTA blk owns hidden units [blk*8, blk*8+8) across 4 gates (32 Whh rows).
// Whh slice lives in SMEM (loaded once). 512 threads:
//   q = tid>>7 (K quarter), idx = tid&127, r = idx>>2 (gate row), bq = idx&3.
//   Thread computes row r for batches {bq, bq+4, bq+8, bq+12} over 256 ks,
//   with k-pairs packed into fma.rn.f32x2. K-quarters reduced via smem.
__global__ void __launch_bounds__(512, 1) recur_k(
    const float* __restrict__ xg,      // [16384][4096]
    const float* __restrict__ whh,     // [4096][1024]
    const float* __restrict__ hinit,   // [16][1024] or null (zeros)
    const float* __restrict__ cinit,   // [16][1024] or null (zeros)
    float* __restrict__ seq,           // [16384][1024]
    float* __restrict__ hfin, float* __restrict__ cfin)  // [16][1024] or null
{
    extern __shared__ float sm[];
    float* w_s = sm;                         // 32 * 1036
    float* hs  = sm + 32 * STR_W;            // 16 * 1036
    float* gsh = hs + 16 * STR_H;            // 512  (32 rows x 16 batch)
    float* red = gsh + 512;                  // 2048 (512 threads x 4)

    const int tid = threadIdx.x;
    const int blk = blockIdx.x;

    // prologue: stage Whh slice into smem (coalesced per row)
    {
        int wr = tid >> 4, wc = tid & 15;
        int grow = (wr >> 3) * 1024 + blk * 8 + (wr & 7);
        const float4* src = (const float4*)(whh + (size_t)grow * 1024);
        #pragma unroll
        for (int j = 0; j < 16; j++) {
            float4 v = src[wc + j * 16];
            *(float4*)&w_s[wr * STR_W + (wc + j * 16) * 4] = v;
        }
    }

    const int q = tid >> 7, idx = tid & 127;
    const int r = idx >> 2, bq = idx & 3;
    const int kbase = q * 256;
    const float* wrow = w_s + r * STR_W;
    const int grow_r = (r >> 3) * 1024 + blk * 8 + (r & 7);  // xg row for reducer

    const int u = tid >> 4, ub = tid & 15;   // updater mapping (tid<128: u 0..7)
    const int hu = blk * 8 + u;

    float creg = 0.f, hlast = 0.f;
    unsigned gen = *(volatile unsigned*)&g_gen;  // stable: no CTA can advance yet

    if (tid < 128) {
        float h0 = 0.f;
        if (cinit) creg = cinit[ub * 1024 + hu];
        if (hinit) h0   = hinit[ub * 1024 + hu];
        g_hbuf[0][ub * 1024 + hu] = h0;
    }
    gen++; gridbar(gen);

    for (int t = 0; t < 1024; t++) {
        // prefetch xg for this step's reducers (hidden under the FMA loop)
        float xr0, xr1, xr2, xr3;
        if (tid < 128) {
            const float* xp = xg + ((size_t)(t * 16 + bq)) * 4096 + grow_r;
            xr0 = __ldcg(xp);
            xr1 = __ldcg(xp + 4  * 4096);
            xr2 = __ldcg(xp + 8  * 4096);
            xr3 = __ldcg(xp + 12 * 4096);
        }
        // coalesced copy of h (batch-major) into padded smem
        {
            const float4* hb = (const float4*)g_hbuf[t & 1];
            #pragma unroll
            for (int i = 0; i < 8; i++) {
                int v = tid + i * 512;          // 4096 float4s
                float4 hv = __ldcg(hb + v);
                int b = v >> 8, k4 = v & 255;
                *(float4*)&hs[b * STR_H + k4 * 4] = hv;
            }
        }
        __syncthreads();

        // packed-k FMA2 mainloop: 8 FMA2 (=16 FMA) per k4 per thread
        unsigned long long a0 = 0ull, a1 = 0ull, a2 = 0ull, a3 = 0ull;
        const float* h0p = hs + (bq     ) * STR_H;
        const float* h1p = hs + (bq +  4) * STR_H;
        const float* h2p = hs + (bq +  8) * STR_H;
        const float* h3p = hs + (bq + 12) * STR_H;
        #pragma unroll 4
        for (int k = kbase; k < kbase + 256; k += 4) {
            ulonglong2 wv = *(const ulonglong2*)&wrow[k];
            ulonglong2 h0 = *(const ulonglong2*)&h0p[k];
            ulonglong2 h1 = *(const ulonglong2*)&h1p[k];
            ulonglong2 h2 = *(const ulonglong2*)&h2p[k];
            ulonglong2 h3 = *(const ulonglong2*)&h3p[k];
            FMA2(a0, wv.x, h0.x); FMA2(a0, wv.y, h0.y);
            FMA2(a1, wv.x, h1.x); FMA2(a1, wv.y, h1.y);
            FMA2(a2, wv.x, h2.x); FMA2(a2, wv.y, h2.y);
            FMA2(a3, wv.x, h3.x); FMA2(a3, wv.y, h3.y);
        }
        float p0, p1, p2, p3;
        { float lo, hi;
          UNPK(lo, hi, a0); p0 = lo + hi;
          UNPK(lo, hi, a1); p1 = lo + hi;
          UNPK(lo, hi, a2); p2 = lo + hi;
          UNPK(lo, hi, a3); p3 = lo + hi; }
        float4 pv = {p0, p1, p2, p3};
        *(float4*)&red[tid * 4] = pv;
        __syncthreads();

        if (tid < 128) {     // reduce K quarters + add xg -> gate preacts
            float4 s0 = *(const float4*)&red[tid * 4];
            float4 s1 = *(const float4*)&red[512  + tid * 4];
            float4 s2 = *(const float4*)&red[1024 + tid * 4];
            float4 s3 = *(const float4*)&red[1536 + tid * 4];
            gsh[r * 16 + bq     ] = s0.x + s1.x + s2.x + s3.x + xr0;
            gsh[r * 16 + bq +  4] = s0.y + s1.y + s2.y + s3.y + xr1;
            gsh[r * 16 + bq +  8] = s0.z + s1.z + s2.z + s3.z + xr2;
            gsh[r * 16 + bq + 12] = s0.w + s1.w + s2.w + s3.w + xr3;
        }
        __syncthreads();

        if (tid < 128) {     // cell update (gate order: i, f, g, o)
            float gi = gsh[(u     ) * 16 + ub];
            float gf = gsh[(8  + u) * 16 + ub];
            float gg = gsh[(16 + u) * 16 + ub];
            float go = gsh[(24 + u) * 16 + ub];
            float si = 1.f / (1.f + __expf(-gi));
            float sf = 1.f / (1.f + __expf(-gf));
            float so = 1.f / (1.f + __expf(-go));
            creg = sf * creg + si * tanhf(gg);
            float hv = so * tanhf(creg);
            hlast = hv;
            g_hbuf[(t + 1) & 1][ub * 1024 + hu] = hv;
            seq[((size_t)(t * 16 + ub)) * 1024 + hu] = hv;
        }
        gen++; gridbar(gen);
    }
    if (tid < 128) {
        if (hfin) hfin[ub * 1024 + hu] = hlast;
        if (cfin) cfin[ub * 1024 + hu] = creg;
    }
}

// ----------------- (B,T,C) -> (B,C,T) transpose ----------------------------
__global__ void __launch_bounds__(256) trans_k(const float* __restrict__ scr,
                                               float* __restrict__ out) {
    __shared__ float tile[32][33];
    int b  = blockIdx.z;
    int t0 = blockIdx.x * 32, n0 = blockIdx.y * 32;
    int tx = threadIdx.x, ty = threadIdx.y;
    for (int i = ty; i < 32; i += 8)
        tile[i][tx] = scr[((size_t)(t0 + i) * 16 + b) * 256 + n0 + tx];
    __syncthreads();
    for (int i = ty; i < 32; i += 8)
        out[((size_t)b * 256 + n0 + i) * 1024 + t0 + tx] = tile[tx][i];
}

// ----------------- driver ---------------------------------------------------
extern "C" void kernel_launch(void* const* d_in, const int* in_sizes, int n_in,
                              void* d_out, int out_size) {
    (void)in_sizes; (void)n_in; (void)out_size;
    const int*   x       = (const int*)  d_in[0];
    const float* enc_emb = (const float*)d_in[1];
    const float* dec_emb = (const float*)d_in[2];
    const float* eW0 = (const float*)d_in[3],  *eU0 = (const float*)d_in[4];
    const float* eb0 = (const float*)d_in[5],  *ec0 = (const float*)d_in[6];
    const float* eW1 = (const float*)d_in[7],  *eU1 = (const float*)d_in[8];
    const float* eb1 = (const float*)d_in[9],  *ec1 = (const float*)d_in[10];
    const float* dW0 = (const float*)d_in[11], *dU0 = (const float*)d_in[12];
    const float* db0 = (const float*)d_in[13], *dc0 = (const float*)d_in[14];
    const float* dW1 = (const float*)d_in[15], *dU1 = (const float*)d_in[16];
    const float* db1 = (const float*)d_in[17], *dc1 = (const float*)d_in[18];
    const float* outW = (const float*)d_in[19];
    const float* outb = (const float*)d_in[20];
    float* out = (float*)d_out;

    const int RSMEM = (32 * STR_W + 16 * STR_H + 512 + 2048) * 4;  // 209,152 B

    static int smem_set = 0;
    if (!smem_set) {
        cudaFuncSetAttribute(recur_k, cudaFuncAttributeMaxDynamicSharedMemorySize, RSMEM);
        smem_set = 1;
    }

    float *emb, *seqA, *seqB, *xgp, *hf0, *cf0, *hf1, *cf1;
    cudaGetSymbolAddress((void**)&emb,  g_emb);
    cudaGetSymbolAddress((void**)&seqA, g_seqA);
    cudaGetSymbolAddress((void**)&seqB, g_seqB);
    cudaGetSymbolAddress((void**)&xgp,  g_xg);
    cudaGetSymbolAddress((void**)&hf0,  g_hf0);
    cudaGetSymbolAddress((void**)&cf0,  g_cf0);
    cudaGetSymbolAddress((void**)&hf1,  g_hf1);
    cudaGetSymbolAddress((void**)&cf1,  g_cf1);

    const dim3 gBig(32, 128), gOut(2, 128);

    // Encoder
    embed_k<<<16384, 128>>>(enc_emb, x);
    sgemm_nt<<<gBig, 256>>>(emb,  eW0, eb0, ec0, xgp, 512,  4096);
    recur_k<<<NCTA, 512, RSMEM>>>(xgp, eU0, nullptr, nullptr, seqA, hf0, cf0);
    sgemm_nt<<<gBig, 256>>>(seqA, eW1, eb1, ec1, xgp, 1024, 4096);
    recur_k<<<NCTA, 512, RSMEM>>>(xgp, eU1, nullptr, nullptr, seqB, hf1, cf1);
    // Decoder (teacher forcing, states from encoder)
    embed_k<<<16384, 128>>>(dec_emb, x);
    sgemm_nt<<<gBig, 256>>>(emb,  dW0, db0, dc0, xgp, 512,  4096);
    recur_k<<<NCTA, 512, RSMEM>>>(xgp, dU0, hf0, cf0, seqA, nullptr, nullptr);
    sgemm_nt<<<gBig, 256>>>(seqA, dW1, db1, dc1, xgp, 1024, 4096);
    recur_k<<<NCTA, 512, RSMEM>>>(xgp, dU1, hf1, cf1, seqB, nullptr, nullptr);
    // Output projection into scratch (g_emb), then transpose to (B,C,T)
    sgemm_nt<<<gOut, 256>>>(seqB, outW, outb, nullptr, emb, 1024, 256);
    trans_k<<<dim3(32, 8, 16), dim3(32, 8)>>>(emb, out);
}